// round 6
// baseline (speedup 1.0000x reference)
#include <cuda_runtime.h>
#include <cstdint>

#define BS 128
#define NC 1024
#define U  512
#define F  512
#define FOURU 2048
#define KTOT 1024

// ---------------- scratch (no allocations allowed) ----------------
__device__ float g_h0[BS * U];
__device__ float g_c0[BS * U];
__device__ int   g_idx[BS];
__device__ float g_zpart[4][BS * FOURU];   // z = sum of 4 K-slices + bias

// ---------------- helpers ----------------
__device__ __forceinline__ unsigned long long dup2(float v) {
    unsigned long long r;
    asm("mov.b64 %0, {%1, %1};" : "=l"(r) : "f"(v));
    return r;
}
__device__ __forceinline__ void fma2(unsigned long long& d,
                                     unsigned long long a,
                                     unsigned long long b) {
    asm("fma.rn.f32x2 %0, %1, %2, %3;" : "=l"(d) : "l"(a), "l"(b), "l"(d));
}
__device__ __forceinline__ void atomicMaxFloat(float* addr, float val) {
    int* ia = (int*)addr;
    int old = *ia;
    while (__int_as_float(old) < val) {
        int assumed = old;
        old = atomicCAS(ia, assumed, __float_as_int(val));
        if (old == assumed) break;
    }
}
__device__ __forceinline__ float fsig(float x) {
    float e, r;
    asm("ex2.approx.ftz.f32 %0, %1;" : "=f"(e) : "f"(-x * 1.4426950408889634f));
    asm("rcp.approx.ftz.f32 %0, %1;" : "=f"(r) : "f"(1.0f + e));
    return r;
}
__device__ __forceinline__ float ftanh_fast(float x) {
    return 2.0f * fsig(2.0f * x) - 1.0f;
}

// ---------------- K1: per-row argmax of logits + gather states ----------------
__global__ void k_argmax_gather(const float* __restrict__ logits,
                                const float* __restrict__ h_states,
                                const float* __restrict__ c_states) {
    const int b = blockIdx.x;
    const int t = threadIdx.x;                 // 256 threads
    const float* row = logits + b * NC;

    float best = -3.4e38f;
    int   bi   = 0x7fffffff;
#pragma unroll
    for (int j = 0; j < NC; j += 256) {
        float v = row[j + t];
        int   i = j + t;
        if (v > best || (v == best && i < bi)) { best = v; bi = i; }
    }
#pragma unroll
    for (int off = 16; off; off >>= 1) {
        float ov = __shfl_down_sync(0xffffffffu, best, off);
        int   oi = __shfl_down_sync(0xffffffffu, bi,   off);
        if (ov > best || (ov == best && oi < bi)) { best = ov; bi = oi; }
    }
    __shared__ float sv[8];
    __shared__ int   si[8];
    __shared__ int   s_idx;
    if ((t & 31) == 0) { sv[t >> 5] = best; si[t >> 5] = bi; }
    __syncthreads();
    if (t == 0) {
        best = sv[0]; bi = si[0];
#pragma unroll
        for (int w = 1; w < 8; ++w)
            if (sv[w] > best || (sv[w] == best && si[w] < bi)) { best = sv[w]; bi = si[w]; }
        s_idx = bi;
        g_idx[b] = bi;
    }
    __syncthreads();
    const int idx = s_idx;

    const float4* hs = (const float4*)(h_states + idx * U);
    const float4* cs = (const float4*)(c_states + idx * U);
    float4* hd = (float4*)(g_h0 + b * U);
    float4* cd = (float4*)(g_c0 + b * U);
    if (t < U / 4) { hd[t] = hs[t]; cd[t] = cs[t]; }
}

// ---------------- K2: copy states into output (base for scatter-max) ----------------
__global__ void k_copy_states(const float* __restrict__ h_states,
                              const float* __restrict__ c_states,
                              float* __restrict__ out_newh,
                              float* __restrict__ out_newc) {
    int i = blockIdx.x * blockDim.x + threadIdx.x;   // over NC*U/4 float4s
    if (i < NC * U / 4) {
        ((float4*)out_newh)[i] = ((const float4*)h_states)[i];
        ((float4*)out_newc)[i] = ((const float4*)c_states)[i];
    }
}

// ---------------- K3: split-K fused GEMM  zpart[kc] = A_kc @ B_kc ----------------
// Combined K=1024: slices 0,1 -> x @ kernel (K halves), 2,3 -> h0 @ rec_kernel.
// Tile 128(M) x 32(N) x 16(K), 128 threads, 8x4 outputs/thread, f32x2 FFMA.
#define TM 128
#define TN 32
#define TK 16
#define KS 256
#define NIT (KS / TK)
#define APAD 2

__global__ __launch_bounds__(128) void k_gemm(const float* __restrict__ x,
                                              const float* __restrict__ kernelW,
                                              const float* __restrict__ recW) {
    const int kc = blockIdx.y;                       // 0..3
    const float* __restrict__ A = (kc < 2) ? x : g_h0;       // stride 512
    const float* __restrict__ B = (kc < 2) ? kernelW : recW; // stride 2048
    const int koff = (kc & 1) * KS;
    float* __restrict__ Zout = g_zpart[kc];

    __shared__ unsigned long long As2[2][TK][TM + APAD];  // A dup'd into f32x2
    __shared__ unsigned long long Bs[2][TK][TN / 2];      // B as f32 pairs

    const int t = threadIdx.x;
    const int n_blk = blockIdx.x * TN;

    // compute coords: 16 m-groups x 8 n-groups
    const int mt8 = (t >> 3) * 8;        // row base 0..120
    const int nt  = t & 7;               // col-pair-pair 0..7 (4 cols)

    // loader coords
    const int arow = t >> 2;             // 0..31 (+32*i)
    const int akq  = (t & 3) * 4;        // k 0,4,8,12
    const int bk   = t >> 3;             // 0..15
    const int bn2  = (t & 7) * 2;        // u64 col index (2 cols each)

    unsigned long long acc[8][2];
#pragma unroll
    for (int r = 0; r < 8; ++r) { acc[r][0] = 0ull; acc[r][1] = 0ull; }

    const float* Aptr = A + arow * 512 + koff + akq;
    const float* Bptr = B + (koff + bk) * FOURU + n_blk + bn2 * 2;

    float4 a_pre[4];
    float4 b_pre;

    // prologue: load tile 0
#pragma unroll
    for (int i = 0; i < 4; ++i) a_pre[i] = *(const float4*)(Aptr + i * 32 * 512);
    b_pre = *(const float4*)Bptr;
#pragma unroll
    for (int i = 0; i < 4; ++i) {
        As2[0][akq + 0][arow + i * 32] = dup2(a_pre[i].x);
        As2[0][akq + 1][arow + i * 32] = dup2(a_pre[i].y);
        As2[0][akq + 2][arow + i * 32] = dup2(a_pre[i].z);
        As2[0][akq + 3][arow + i * 32] = dup2(a_pre[i].w);
    }
    *(ulonglong2*)&Bs[0][bk][bn2] = *(ulonglong2*)&b_pre;
    __syncthreads();

    int buf = 0;
    for (int it = 0; it < NIT; ++it) {
        if (it + 1 < NIT) {
            Aptr += TK;
            Bptr += TK * FOURU;
#pragma unroll
            for (int i = 0; i < 4; ++i) a_pre[i] = *(const float4*)(Aptr + i * 32 * 512);
            b_pre = *(const float4*)Bptr;
        }

#pragma unroll
        for (int kk = 0; kk < TK; ++kk) {
            const unsigned long long* Ar = &As2[buf][kk][mt8];
            ulonglong2 a01 = *(const ulonglong2*)(Ar);
            ulonglong2 a23 = *(const ulonglong2*)(Ar + 2);
            ulonglong2 a45 = *(const ulonglong2*)(Ar + 4);
            ulonglong2 a67 = *(const ulonglong2*)(Ar + 6);
            ulonglong2 b01 = *(const ulonglong2*)&Bs[buf][kk][nt * 2];
            fma2(acc[0][0], a01.x, b01.x); fma2(acc[0][1], a01.x, b01.y);
            fma2(acc[1][0], a01.y, b01.x); fma2(acc[1][1], a01.y, b01.y);
            fma2(acc[2][0], a23.x, b01.x); fma2(acc[2][1], a23.x, b01.y);
            fma2(acc[3][0], a23.y, b01.x); fma2(acc[3][1], a23.y, b01.y);
            fma2(acc[4][0], a45.x, b01.x); fma2(acc[4][1], a45.x, b01.y);
            fma2(acc[5][0], a45.y, b01.x); fma2(acc[5][1], a45.y, b01.y);
            fma2(acc[6][0], a67.x, b01.x); fma2(acc[6][1], a67.x, b01.y);
            fma2(acc[7][0], a67.y, b01.x); fma2(acc[7][1], a67.y, b01.y);
        }

        if (it + 1 < NIT) {
            const int nb = buf ^ 1;
#pragma unroll
            for (int i = 0; i < 4; ++i) {
                As2[nb][akq + 0][arow + i * 32] = dup2(a_pre[i].x);
                As2[nb][akq + 1][arow + i * 32] = dup2(a_pre[i].y);
                As2[nb][akq + 2][arow + i * 32] = dup2(a_pre[i].z);
                As2[nb][akq + 3][arow + i * 32] = dup2(a_pre[i].w);
            }
            *(ulonglong2*)&Bs[nb][bk][bn2] = *(ulonglong2*)&b_pre;
        }
        __syncthreads();
        buf ^= 1;
    }

#pragma unroll
    for (int r = 0; r < 8; ++r) {
        float* zr = Zout + (mt8 + r) * FOURU + n_blk + nt * 4;
        ulonglong2 v; v.x = acc[r][0]; v.y = acc[r][1];
        *(ulonglong2*)zr = v;
    }
}

// ---------------- K4: gates + LSTM cell + scatter-max (float2) ----------------
__global__ void k_gates_scatter(const float* __restrict__ bias,
                                float* __restrict__ out_h,
                                float* __restrict__ out_newh,
                                float* __restrict__ out_newc) {
    const int i = blockIdx.x * blockDim.x + threadIdx.x;  // 0 .. BS*U/2-1
    const int b = i >> 8;            // / (U/2)
    const int u = (i & 255) * 2;     // unit pair

    const int base = b * FOURU + u;
    float2 zi = make_float2(0.f, 0.f), zf = zi, zg = zi, zo = zi;
#pragma unroll
    for (int p = 0; p < 4; ++p) {
        const float* zp = g_zpart[p] + base;
        float2 a = *(const float2*)(zp);
        float2 bb = *(const float2*)(zp + U);
        float2 c = *(const float2*)(zp + 2 * U);
        float2 d = *(const float2*)(zp + 3 * U);
        zi.x += a.x;  zi.y += a.y;
        zf.x += bb.x; zf.y += bb.y;
        zg.x += c.x;  zg.y += c.y;
        zo.x += d.x;  zo.y += d.y;
    }
    float2 bi = *(const float2*)(bias + u);
    float2 bf = *(const float2*)(bias + u + U);
    float2 bg = *(const float2*)(bias + u + 2 * U);
    float2 bo = *(const float2*)(bias + u + 3 * U);
    float2 c0 = *(const float2*)(g_c0 + b * U + u);

    float h0v, h1v, c0v, c1v;
    {
        float ig = fsig(zi.x + bi.x);
        float fg = fsig(zf.x + bf.x);
        float gg = ftanh_fast(zg.x + bg.x);
        float og = fsig(zo.x + bo.x);
        c0v = fg * c0.x + ig * gg;
        h0v = og * ftanh_fast(c0v);
    }
    {
        float ig = fsig(zi.y + bi.y);
        float fg = fsig(zf.y + bf.y);
        float gg = ftanh_fast(zg.y + bg.y);
        float og = fsig(zo.y + bo.y);
        c1v = fg * c0.y + ig * gg;
        h1v = og * ftanh_fast(c1v);
    }

    *(float2*)(out_h + b * U + u) = make_float2(h0v, h1v);

    const int cls = g_idx[b];
    float* nh = out_newh + cls * U + u;
    float* nc = out_newc + cls * U + u;
    atomicMaxFloat(nh,     h0v);
    atomicMaxFloat(nh + 1, h1v);
    atomicMaxFloat(nc,     c0v);
    atomicMaxFloat(nc + 1, c1v);
}

// ---------------- launch ----------------
extern "C" void kernel_launch(void* const* d_in, const int* in_sizes, int n_in,
                              void* d_out, int out_size) {
    const float* x        = (const float*)d_in[0];
    const float* logits   = (const float*)d_in[1];
    const float* h_states = (const float*)d_in[2];
    const float* c_states = (const float*)d_in[3];
    const float* kernelW  = (const float*)d_in[4];
    const float* recW     = (const float*)d_in[5];
    const float* bias     = (const float*)d_in[6];

    float* out      = (float*)d_out;
    float* out_h    = out;                    // (128, 512)
    float* out_newh = out + BS * U;           // (1024, 512)
    float* out_newc = out + BS * U + NC * U;  // (1024, 512)

    k_argmax_gather<<<BS, 256>>>(logits, h_states, c_states);
    k_copy_states<<<(NC * U / 4 + 255) / 256, 256>>>(h_states, c_states, out_newh, out_newc);
    dim3 g(FOURU / TN, 4, 1);                 // 64 x 4 = 256 blocks
    k_gemm<<<g, 128>>>(x, kernelW, recW);
    k_gates_scatter<<<(BS * U / 2) / 256, 256>>>(bias, out_h, out_newh, out_newc);
}